// round 9
// baseline (speedup 1.0000x reference)
#include <cuda_runtime.h>
#include <cuda_bf16.h>
#include <cstdint>

#define SEQ_LEN 131072
#define NN 256
#define CC 16
#define NF 100
#define ROWS 32
#define TILE 16
#define NTILES 15
#define THREADS 256

typedef unsigned long long ull;

// Scratch (device globals; no runtime allocation)
// g_W16[t][k][c] = W[k][CC+16t+c] * mask  (16 cols per tile, k-major)
__device__ float g_W16[NTILES * NN * TILE];
__device__ int   g_bad;
__device__ int   g_c0_is_W;

// Shared memory layout (bytes), per CTA (4 CTAs/SM: 4 x ~43.4KB = 174KB)
#define VALS_OFF 0            // float [256][32]    = 32768
#define ZB_OFF   32768        // float [4][16][32]  =  8192
#define ESH_OFF  40960        // float [16][32]     =  2048
#define ACT_OFF  43008        // int [240]          =   960
#define XCOL_OFF 43968        // int [101]          =   404
#define SMEM_BYTES 44416

__device__ __forceinline__ ull ffma2(ull a, ull b, ull c) {
    ull d;
    asm("fma.rn.f32x2 %0, %1, %2, %3;" : "=l"(d) : "l"(a), "l"(b), "l"(c));
    return d;
}

__device__ __forceinline__ ull dup2(float w) {
    ull d;
    asm("mov.b64 %0, {%1, %1};" : "=l"(d) : "f"(w));
    return d;
}

__device__ __forceinline__ bool nan_bits(float v) {
    return (__float_as_uint(v) & 0x7fffffffu) > 0x7f800000u;
}

__global__ void init_kernel() { g_bad = 0; g_c0_is_W = 0; }

// Disambiguate W (float32) vs mask (int32 in {0,1}) among the two 65536-elem inputs.
__global__ void detect_kernel(const unsigned int* __restrict__ c0) {
    int idx = blockIdx.x * blockDim.x + threadIdx.x;
    if (idx < NN * NN) {
        if (c0[idx] > 1u) atomicOr(&g_c0_is_W, 1);
    }
}

__global__ void prep_kernel(const void* __restrict__ cand0, const void* __restrict__ cand1) {
    const float* W    = g_c0_is_W ? (const float*)cand0 : (const float*)cand1;
    const int*   mask = g_c0_is_W ? (const int*)cand1   : (const int*)cand0;
    int idx = blockIdx.x * blockDim.x + threadIdx.x;   // (t, k, c)
    if (idx < NTILES * NN * TILE) {
        int t   = idx / (NN * TILE);
        int rem = idx - t * (NN * TILE);
        int k   = rem >> 4;
        int c   = rem & 15;
        int j   = CC + 16 * t + c;
        g_W16[idx] = (mask[k * NN + j] != 0) ? W[k * NN + j] : 0.0f;
    }
}

extern __shared__ char smem[];

__global__ void __launch_bounds__(THREADS, 4)
main_kernel(const float* __restrict__ causes, const float* __restrict__ eps,
            const int* __restrict__ act_id, const int* __restrict__ X_idx,
            const int* __restrict__ y_idx, float* __restrict__ out)
{
    float* vals  = (float*)(smem + VALS_OFF);   // vals[k*32 + r]
    float* zb    = (float*)(smem + ZB_OFF);     // zb[s*512 + c*32 + r]
    float* esh   = (float*)(smem + ESH_OFF);    // esh[c*32 + r]
    int*   actsh = (int*)  (smem + ACT_OFF);
    int*   xcol  = (int*)  (smem + XCOL_OFF);

    const int tid = threadIdx.x;
    const int s0  = blockIdx.x * ROWS;

    // X_idx dtype probe (int32 vs int64): sorted values in [16,255) -> if int64,
    // the second 32-bit word is the zero high half.
    const int xstride = (__ldg(X_idx + 1) == 0) ? 2 : 1;
    if (tid < NN - CC) actsh[tid] = act_id[tid];
    if (tid < NF)      xcol[tid]  = __ldg(X_idx + tid * xstride);
    if (tid == NF)     xcol[NF]   = __ldg(y_idx);

    // zero vals rows CC..255
    {
        float4* v4 = (float4*)(vals + CC * ROWS);
        const int n4 = (NN - CC) * ROWS / 4;
        for (int i = tid; i < n4; i += THREADS) v4[i] = make_float4(0.f, 0.f, 0.f, 0.f);
    }
    // causes -> vals rows 0..15 (transposed: vals[node][row])
    if (tid < ROWS) {
        const float4* cp = (const float4*)(causes + (size_t)(s0 + tid) * CC);
        #pragma unroll
        for (int q = 0; q < 4; q++) {
            float4 c4 = __ldg(cp + q);
            vals[(4*q + 0) * ROWS + tid] = c4.x;
            vals[(4*q + 1) * ROWS + tid] = c4.y;
            vals[(4*q + 2) * ROWS + tid] = c4.z;
            vals[(4*q + 3) * ROWS + tid] = c4.w;
        }
    }

    // GEMM tiling: warp w -> (k-split s = w>>1, col-half b = w&1);
    // lane -> rowpair rg = lane&15 (rows 2rg, 2rg+1), col-quarter ch = lane>>4.
    // Each thread: 2 rows x 4 cols.
    const int lane  = tid & 31;
    const int w     = tid >> 5;
    const int s     = w >> 1;
    const int b     = w & 1;
    const int rg    = lane & 15;
    const int ch    = lane >> 4;
    const int cbase = 8 * b + 4 * ch;

    for (int t = 0; t < NTILES; t++) {
        const int j0 = CC + TILE * t;
        const float* gW = g_W16 + (size_t)t * (NN * TILE);

        __syncthreads();   // prev serial writes to vals visible; zb/esh reusable

        // eps stage for serial phase (warp 0 writes, warp 0 reads later: no extra sync)
        if (tid < ROWS) {
            const float4* ep = (const float4*)(eps + (size_t)(s0 + tid) * (NN - CC) + (j0 - CC));
            #pragma unroll
            for (int q = 0; q < 4; q++) {
                float4 e4 = __ldg(ep + q);
                esh[(4*q + 0) * ROWS + tid] = e4.x;
                esh[(4*q + 1) * ROWS + tid] = e4.y;
                esh[(4*q + 2) * ROWS + tid] = e4.z;
                esh[(4*q + 3) * ROWS + tid] = e4.w;
            }
        }

        // GEMM: zb[s][c][r] = sum_{k in split s} vals[k][r] * W[k][j0+c]
        ull acc0 = 0ull, acc1 = 0ull, acc2 = 0ull, acc3 = 0ull;
        const int kq  = j0 >> 2;
        const int klo = kq * s;
        const int khi = klo + kq;
        #pragma unroll 4
        for (int k = klo; k < khi; k++) {
            ull v = *(const ull*)(vals + k * ROWS + 2 * rg);
            float4 wv = __ldg((const float4*)(gW + k * 16 + cbase));
            acc0 = ffma2(v, dup2(wv.x), acc0);
            acc1 = ffma2(v, dup2(wv.y), acc1);
            acc2 = ffma2(v, dup2(wv.z), acc2);
            acc3 = ffma2(v, dup2(wv.w), acc3);
        }
        {
            float* zbase = zb + s * 512 + cbase * ROWS + 2 * rg;
            *(ull*)(zbase + 0 * ROWS) = acc0;
            *(ull*)(zbase + 1 * ROWS) = acc1;
            *(ull*)(zbase + 2 * ROWS) = acc2;
            *(ull*)(zbase + 3 * ROWS) = acc3;
        }
        __syncthreads();

        // Serial intra-tile resolution (threads 0..31, one row each)
        if (tid < ROWS) {
            const int r = tid;
            float z[16];
            #pragma unroll
            for (int c = 0; c < 16; c++) {
                const float* q = zb + c * ROWS + r;
                z[c] = (q[0] + q[512]) + (q[1024] + q[1536]);
            }
            float e[16];
            #pragma unroll
            for (int c = 0; c < 16; c++) e[c] = esh[c * ROWS + r];
            #pragma unroll
            for (int c = 0; c < 16; c++) {
                float zz = fmaf(0.01f, e[c], z[c]);
                int aid = actsh[j0 - CC + c];
                float v;
                if (aid == 0)      v = zz;
                else if (aid == 1) v = tanhf(zz);
                else if (aid == 2) v = (zz > 0.0f) ? zz : (zz == zz ? 0.0f : zz);  // NaN-propagating relu
                else               v = 1.0f / (1.0f + __expf(-zz));
                vals[(j0 + c) * ROWS + r] = v;
                #pragma unroll
                for (int c2 = c + 1; c2 < 16; c2++) {
                    float wv2 = __ldg(gW + (j0 + c) * 16 + c2);
                    z[c2] = fmaf(wv2, v, z[c2]);
                }
            }
        }
    }
    __syncthreads();

    // Gather outputs: X = vals[:, X_idx], y = vals[:, y_idx]
    float* outX = out;
    float* outY = out + (size_t)SEQ_LEN * NF;
    bool bad = false;
    for (int i = tid; i < ROWS * NF; i += THREADS) {
        int r = i / NF;
        int f = i - r * NF;
        float v = vals[xcol[f] * ROWS + r];
        bad |= nan_bits(v);
        outX[(size_t)s0 * NF + i] = v;
    }
    if (tid < ROWS) {
        float v = vals[xcol[NF] * ROWS + tid];
        bad |= nan_bits(v);
        outY[s0 + tid] = v;
    }
    if (__syncthreads_or((int)bad) && tid == 0) atomicOr(&g_bad, 1);
}

__global__ void fixup_kernel(float* __restrict__ out) {
    if (g_bad == 0) return;
    const size_t nx = (size_t)SEQ_LEN * NF;
    const size_t total = nx + (size_t)SEQ_LEN;
    for (size_t i = (size_t)blockIdx.x * blockDim.x + threadIdx.x;
         i < total; i += (size_t)gridDim.x * blockDim.x) {
        out[i] = (i < nx) ? 0.0f : -100.0f;
    }
}

extern "C" void kernel_launch(void* const* d_in, const int* in_sizes, int n_in,
                              void* d_out, int out_size) {
    // Identify inputs by element count (robust to metadata ordering).
    const float* causes = nullptr;
    const float* eps    = nullptr;
    const int*   act    = nullptr;
    const int*   X_idx  = nullptr;
    const int*   y_idx  = nullptr;
    const void*  cand0  = nullptr;   // one of {W, mask}
    const void*  cand1  = nullptr;   // the other
    for (int i = 0; i < n_in; i++) {
        int sz = in_sizes[i];
        if      (sz == SEQ_LEN * CC)        causes = (const float*)d_in[i];
        else if (sz == SEQ_LEN * (NN - CC)) eps    = (const float*)d_in[i];
        else if (sz == NN - CC)             act    = (const int*)d_in[i];
        else if (sz == NF)                  X_idx  = (const int*)d_in[i];
        else if (sz == 1)                   y_idx  = (const int*)d_in[i];
        else if (sz == NN * NN) {
            if (!cand0) cand0 = d_in[i]; else cand1 = d_in[i];
        }
    }
    float* out = (float*)d_out;

    cudaFuncSetAttribute(main_kernel, cudaFuncAttributeMaxDynamicSharedMemorySize, SMEM_BYTES);

    init_kernel<<<1, 1>>>();
    detect_kernel<<<NN, NN>>>((const unsigned int*)cand0);
    prep_kernel<<<(NTILES * NN * TILE + 255) / 256, 256>>>(cand0, cand1);
    main_kernel<<<SEQ_LEN / ROWS, THREADS, SMEM_BYTES>>>(causes, eps, act, X_idx, y_idx, out);
    fixup_kernel<<<2048, 256>>>(out);
}

// round 11
// speedup vs baseline: 1.4045x; 1.4045x over previous
#include <cuda_runtime.h>
#include <cuda_bf16.h>
#include <cstdint>

#define SEQ_LEN 131072
#define NN 256
#define CC 16
#define NF 100
#define ROWS 64
#define TILE 16
#define NTILES 15
#define THREADS 256

typedef unsigned long long ull;

// Scratch (device globals; no runtime allocation)
// g_W16[t][k][c] = W[k][CC+16t+c] * mask  (16 cols per tile, k-major)
__device__ float g_W16[NTILES * NN * TILE];
__device__ int   g_bad;
__device__ int   g_c0_is_W;

// Shared memory layout (bytes), per CTA (2 CTAs/SM)
#define VALS_OFF 0            // float [256][64]   = 65536
#define ZB_OFF   65536        // float [3][16][64] = 12288
#define ACT_OFF  77824        // int [240]         =   960
#define XCOL_OFF 78784        // int [101]         =   404
#define SMEM_BYTES 79232

__device__ __forceinline__ ull ffma2(ull a, ull b, ull c) {
    ull d;
    asm("fma.rn.f32x2 %0, %1, %2, %3;" : "=l"(d) : "l"(a), "l"(b), "l"(c));
    return d;
}

__device__ __forceinline__ ull dup2(float w) {
    ull d;
    asm("mov.b64 %0, {%1, %1};" : "=l"(d) : "f"(w));
    return d;
}

__device__ __forceinline__ bool nan_bits(float v) {
    return (__float_as_uint(v) & 0x7fffffffu) > 0x7f800000u;
}

__global__ void init_kernel() { g_bad = 0; g_c0_is_W = 0; }

// Disambiguate W (float32) vs mask (int32 in {0,1}) among the two 65536-elem inputs.
__global__ void detect_kernel(const unsigned int* __restrict__ c0) {
    int idx = blockIdx.x * blockDim.x + threadIdx.x;
    if (idx < NN * NN) {
        if (c0[idx] > 1u) atomicOr(&g_c0_is_W, 1);
    }
}

__global__ void prep_kernel(const void* __restrict__ cand0, const void* __restrict__ cand1) {
    const float* W    = g_c0_is_W ? (const float*)cand0 : (const float*)cand1;
    const int*   mask = g_c0_is_W ? (const int*)cand1   : (const int*)cand0;
    int idx = blockIdx.x * blockDim.x + threadIdx.x;   // (t, k, c)
    if (idx < NTILES * NN * TILE) {
        int t   = idx / (NN * TILE);
        int rem = idx - t * (NN * TILE);
        int k   = rem >> 4;
        int c   = rem & 15;
        int j   = CC + 16 * t + c;
        g_W16[idx] = (mask[k * NN + j] != 0) ? W[k * NN + j] : 0.0f;
    }
}

extern __shared__ char smem[];

__global__ void __launch_bounds__(THREADS, 2)
main_kernel(const float* __restrict__ causes, const float* __restrict__ eps,
            const int* __restrict__ act_id, const int* __restrict__ X_idx,
            const int* __restrict__ y_idx, float* __restrict__ out)
{
    float* vals  = (float*)(smem + VALS_OFF);   // vals[k*64 + r]
    float* zb    = (float*)(smem + ZB_OFF);     // zb[s*1024 + c*64 + r]
    int*   actsh = (int*)  (smem + ACT_OFF);
    int*   xcol  = (int*)  (smem + XCOL_OFF);

    const int tid = threadIdx.x;
    const int s0  = blockIdx.x * ROWS;

    // X_idx dtype probe (int32 vs int64): sorted values in [16,255) -> if int64,
    // the second 32-bit word is the zero high half.
    const int xstride = (__ldg(X_idx + 1) == 0) ? 2 : 1;
    if (tid < NN - CC) actsh[tid] = act_id[tid];
    if (tid < NF)      xcol[tid]  = __ldg(X_idx + tid * xstride);
    if (tid == NF)     xcol[NF]   = __ldg(y_idx);

    // zero vals rows CC..255
    {
        float4* v4 = (float4*)(vals + CC * ROWS);
        const int n4 = (NN - CC) * ROWS / 4;
        for (int i = tid; i < n4; i += THREADS) v4[i] = make_float4(0.f, 0.f, 0.f, 0.f);
    }
    // causes -> vals rows 0..15 (transposed: vals[node][row])
    if (tid < ROWS) {
        const float4* cp = (const float4*)(causes + (size_t)(s0 + tid) * CC);
        #pragma unroll
        for (int q = 0; q < 4; q++) {
            float4 c4 = __ldg(cp + q);
            vals[(4*q + 0) * ROWS + tid] = c4.x;
            vals[(4*q + 1) * ROWS + tid] = c4.y;
            vals[(4*q + 2) * ROWS + tid] = c4.z;
            vals[(4*q + 3) * ROWS + tid] = c4.w;
        }
    }

    const int w    = tid >> 5;
    const int lane = tid & 31;

    // Workers (warps 2..7): 3 k-splits x 2 col-halves; thread = 4 rows x 4 cols.
    const int wl    = w - 2;
    const int s     = wl >> 1;          // k-split 0..2
    const int b     = wl & 1;           // col half
    const int rg    = lane & 15;        // rows 4rg..4rg+3
    const int ch    = lane >> 4;        // col quarter
    const int cbase = 8 * b + 4 * ch;

    // Serial warps (0..1): row r = tid (0..63); eps for the tile being resolved
    // next is prefetched one iteration ahead into ecur.
    float ecur[16];

    for (int t = 0; t < NTILES; t++) {
        const int j0 = CC + TILE * t;
        const float* gW = g_W16 + (size_t)t * (NN * TILE);

        __syncthreads();   // zb for tile t-1 complete; vals cols < j0-16 visible

        if (w >= 2) {
            // ---- Phase 1, workers: GEMM main over k in third s of [0, j0-16) ----
            ull a0 = 0ull, a1 = 0ull, a2 = 0ull, a3 = 0ull;
            ull b0 = 0ull, b1 = 0ull, b2 = 0ull, b3 = 0ull;
            const int L   = j0 - TILE;
            const int klo = (L * s) / 3;
            const int khi = (L * (s + 1)) / 3;
            #pragma unroll 4
            for (int k = klo; k < khi; k++) {
                ulonglong2 v = *(const ulonglong2*)(vals + k * ROWS + 4 * rg);
                float4 wv = __ldg((const float4*)(gW + k * 16 + cbase));
                ull w0 = dup2(wv.x), w1 = dup2(wv.y), w2 = dup2(wv.z), w3 = dup2(wv.w);
                a0 = ffma2(v.x, w0, a0); b0 = ffma2(v.y, w0, b0);
                a1 = ffma2(v.x, w1, a1); b1 = ffma2(v.y, w1, b1);
                a2 = ffma2(v.x, w2, a2); b2 = ffma2(v.y, w2, b2);
                a3 = ffma2(v.x, w3, a3); b3 = ffma2(v.y, w3, b3);
            }
            __syncthreads();   // serial warp finished writing vals cols [j0-16, j0)
            // ---- Phase 2, workers: GEMM tail over third s of [j0-16, j0) ----
            const int klo2 = j0 - TILE + (TILE * s) / 3;
            const int khi2 = j0 - TILE + (TILE * (s + 1)) / 3;
            #pragma unroll
            for (int k = klo2; k < khi2; k++) {
                ulonglong2 v = *(const ulonglong2*)(vals + k * ROWS + 4 * rg);
                float4 wv = __ldg((const float4*)(gW + k * 16 + cbase));
                ull w0 = dup2(wv.x), w1 = dup2(wv.y), w2 = dup2(wv.z), w3 = dup2(wv.w);
                a0 = ffma2(v.x, w0, a0); b0 = ffma2(v.y, w0, b0);
                a1 = ffma2(v.x, w1, a1); b1 = ffma2(v.y, w1, b1);
                a2 = ffma2(v.x, w2, a2); b2 = ffma2(v.y, w2, b2);
                a3 = ffma2(v.x, w3, a3); b3 = ffma2(v.y, w3, b3);
            }
            float* zbase = zb + s * 1024 + cbase * ROWS + 4 * rg;
            ulonglong2 t0; t0.x = a0; t0.y = b0;
            ulonglong2 t1; t1.x = a1; t1.y = b1;
            ulonglong2 t2; t2.x = a2; t2.y = b2;
            ulonglong2 t3; t3.x = a3; t3.y = b3;
            *(ulonglong2*)(zbase + 0 * ROWS) = t0;
            *(ulonglong2*)(zbase + 1 * ROWS) = t1;
            *(ulonglong2*)(zbase + 2 * ROWS) = t2;
            *(ulonglong2*)(zbase + 3 * ROWS) = t3;
        } else {
            // ---- Phase 1, serial warps ----
            const int r = tid;   // 0..63
            // Prefetch eps for THIS tile (used when resolving tile t at iter t+1 /
            // epilogue). Issued early; consumed next iteration.
            float enext[16];
            {
                const float4* ep = (const float4*)(eps + (size_t)(s0 + r) * (NN - CC) + (j0 - CC));
                float4 q0 = __ldg(ep), q1 = __ldg(ep + 1), q2 = __ldg(ep + 2), q3 = __ldg(ep + 3);
                *(float4*)(enext + 0)  = q0; *(float4*)(enext + 4)  = q1;
                *(float4*)(enext + 8)  = q2; *(float4*)(enext + 12) = q3;
            }
            if (t > 0) {
                // Resolve tile t-1 (cols jp..jp+15), zb from previous iteration.
                const int jp = j0 - TILE;
                const float* gWp = g_W16 + (size_t)(t - 1) * (NN * TILE);
                float z[16];
                #pragma unroll
                for (int c = 0; c < 16; c++) {
                    const float* q = zb + c * ROWS + r;
                    z[c] = (q[0] + q[1024]) + q[2048];
                }
                #pragma unroll
                for (int c = 0; c < 16; c++) {
                    float zz = fmaf(0.01f, ecur[c], z[c]);
                    int aid = actsh[jp - CC + c];
                    float v;
                    if (aid == 0)      v = zz;
                    else if (aid == 1) v = tanhf(zz);
                    else if (aid == 2) v = (zz > 0.0f) ? zz : (zz == zz ? 0.0f : zz);
                    else               v = 1.0f / (1.0f + __expf(-zz));
                    vals[(jp + c) * ROWS + r] = v;
                    #pragma unroll
                    for (int c2 = c + 1; c2 < 16; c2++) {
                        float wv2 = __ldg(gWp + (jp + c) * 16 + c2);
                        z[c2] = fmaf(wv2, v, z[c2]);
                    }
                }
            }
            #pragma unroll
            for (int c = 0; c < 16; c++) ecur[c] = enext[c];
            __syncthreads();   // matches workers' mid-phase barrier
            // Phase 2: serial warps idle (workers run tail + store zb)
        }
    }
    __syncthreads();   // zb for last tile complete

    // Epilogue: resolve last tile (serial warps), using ecur prefetched at t=14.
    if (tid < ROWS) {
        const int r = tid;
        const int jp = CC + TILE * (NTILES - 1);
        const float* gWp = g_W16 + (size_t)(NTILES - 1) * (NN * TILE);
        float z[16];
        #pragma unroll
        for (int c = 0; c < 16; c++) {
            const float* q = zb + c * ROWS + r;
            z[c] = (q[0] + q[1024]) + q[2048];
        }
        #pragma unroll
        for (int c = 0; c < 16; c++) {
            float zz = fmaf(0.01f, ecur[c], z[c]);
            int aid = actsh[jp - CC + c];
            float v;
            if (aid == 0)      v = zz;
            else if (aid == 1) v = tanhf(zz);
            else if (aid == 2) v = (zz > 0.0f) ? zz : (zz == zz ? 0.0f : zz);
            else               v = 1.0f / (1.0f + __expf(-zz));
            vals[(jp + c) * ROWS + r] = v;
            #pragma unroll
            for (int c2 = c + 1; c2 < 16; c2++) {
                float wv2 = __ldg(gWp + (jp + c) * 16 + c2);
                z[c2] = fmaf(wv2, v, z[c2]);
            }
        }
    }
    __syncthreads();

    // Gather outputs: X = vals[:, X_idx], y = vals[:, y_idx]
    float* outX = out;
    float* outY = out + (size_t)SEQ_LEN * NF;
    bool bad = false;
    for (int i = tid; i < ROWS * NF; i += THREADS) {
        int r = i / NF;
        int f = i - r * NF;
        float v = vals[xcol[f] * ROWS + r];
        bad |= nan_bits(v);
        outX[(size_t)s0 * NF + i] = v;
    }
    if (tid < ROWS) {
        float v = vals[xcol[NF] * ROWS + tid];
        bad |= nan_bits(v);
        outY[s0 + tid] = v;
    }
    if (__syncthreads_or((int)bad) && tid == 0) atomicOr(&g_bad, 1);
}

__global__ void fixup_kernel(float* __restrict__ out) {
    if (g_bad == 0) return;
    const size_t nx = (size_t)SEQ_LEN * NF;
    const size_t total = nx + (size_t)SEQ_LEN;
    for (size_t i = (size_t)blockIdx.x * blockDim.x + threadIdx.x;
         i < total; i += (size_t)gridDim.x * blockDim.x) {
        out[i] = (i < nx) ? 0.0f : -100.0f;
    }
}

extern "C" void kernel_launch(void* const* d_in, const int* in_sizes, int n_in,
                              void* d_out, int out_size) {
    // Identify inputs by element count (robust to metadata ordering).
    const float* causes = nullptr;
    const float* eps    = nullptr;
    const int*   act    = nullptr;
    const int*   X_idx  = nullptr;
    const int*   y_idx  = nullptr;
    const void*  cand0  = nullptr;   // one of {W, mask}
    const void*  cand1  = nullptr;   // the other
    for (int i = 0; i < n_in; i++) {
        int sz = in_sizes[i];
        if      (sz == SEQ_LEN * CC)        causes = (const float*)d_in[i];
        else if (sz == SEQ_LEN * (NN - CC)) eps    = (const float*)d_in[i];
        else if (sz == NN - CC)             act    = (const int*)d_in[i];
        else if (sz == NF)                  X_idx  = (const int*)d_in[i];
        else if (sz == 1)                   y_idx  = (const int*)d_in[i];
        else if (sz == NN * NN) {
            if (!cand0) cand0 = d_in[i]; else cand1 = d_in[i];
        }
    }
    float* out = (float*)d_out;

    cudaFuncSetAttribute(main_kernel, cudaFuncAttributeMaxDynamicSharedMemorySize, SMEM_BYTES);

    init_kernel<<<1, 1>>>();
    detect_kernel<<<NN, NN>>>((const unsigned int*)cand0);
    prep_kernel<<<(NTILES * NN * TILE + 255) / 256, 256>>>(cand0, cand1);
    main_kernel<<<SEQ_LEN / ROWS, THREADS, SMEM_BYTES>>>(causes, eps, act, X_idx, y_idx, out);
    fixup_kernel<<<2048, 256>>>(out);
}